// round 1
// baseline (speedup 1.0000x reference)
#include <cuda_runtime.h>
#include <cstdint>

#define SEQ 512
#define BATCH 256
#define HID 256
#define N4 1024            // 4 gates * HID
#define OUT_SEQ_ELEMS ((size_t)SEQ * BATCH * HID)   // 33554432

// 512 MB scratch for precomputed  x @ Wx^T + b   laid out [t][b][n], n = gate*256 + j
__device__ float g_xw[(size_t)SEQ * BATCH * N4];

// monotonic grid-barrier ticket counter (never reset; correct across graph replays)
__device__ unsigned long long g_bar_counter = 0ULL;

// ---------------------------------------------------------------------------
// helpers
// ---------------------------------------------------------------------------
__device__ __forceinline__ float sigmoidf_(float x) {
    return __fdividef(1.0f, 1.0f + __expf(-x));
}
__device__ __forceinline__ float tanhf_fast(float x) {
    return 2.0f * sigmoidf_(2.0f * x) - 1.0f;
}

__device__ __forceinline__ void grid_barrier(unsigned nblocks) {
    __threadfence();           // make this thread's global writes visible (L2)
    __syncthreads();           // all threads of CTA have fenced
    if (threadIdx.x == 0) {
        unsigned long long ticket = atomicAdd(&g_bar_counter, 1ULL);
        unsigned long long target = (ticket / nblocks + 1ULL) * (unsigned long long)nblocks;
        while (*((volatile unsigned long long*)&g_bar_counter) < target) {
            __nanosleep(32);
        }
    }
    __syncthreads();
}

// ---------------------------------------------------------------------------
// Phase 1: XW[m][n] = X[m][0:256] @ Wx^T + bias      (m = t*BATCH+b, n = g*256+j)
// 64x64 tile, BK=16, 256 threads, 4x4 per thread, fp32
// ---------------------------------------------------------------------------
__global__ void __launch_bounds__(256)
xw_gemm(const float* __restrict__ X,
        const float* __restrict__ Wf, const float* __restrict__ Wi,
        const float* __restrict__ Wu, const float* __restrict__ Wo,
        const float* __restrict__ bf, const float* __restrict__ bi,
        const float* __restrict__ bu, const float* __restrict__ bo)
{
    __shared__ float As[16][64];
    __shared__ float Bs[16][64];

    const int n0 = blockIdx.x * 64;          // 0..960
    const int m0 = blockIdx.y * 64;          // 0..131008
    const int gate = n0 >> 8;
    const float* __restrict__ W    = (gate == 0) ? Wf : (gate == 1) ? Wi : (gate == 2) ? Wu : Wo;
    const float* __restrict__ bias = (gate == 0) ? bf : (gate == 1) ? bi : (gate == 2) ? bu : bo;
    const int jbase = n0 & 255;

    const int t  = threadIdx.x;
    const int tc = t & 15;                   // col group (4 cols)
    const int tr = t >> 4;                   // row group (4 rows)

    float acc[4][4];
#pragma unroll
    for (int i = 0; i < 4; i++)
#pragma unroll
        for (int j = 0; j < 4; j++) acc[i][j] = 0.0f;

    const int ml = t >> 2;
    const int kl = (t & 3) << 2;

    for (int k0 = 0; k0 < 256; k0 += 16) {
        float4 a = *(const float4*)&X[(size_t)(m0 + ml) * 256 + k0 + kl];
        float4 b = *(const float4*)&W[(size_t)(jbase + ml) * 512 + k0 + kl];
        As[kl + 0][ml] = a.x; As[kl + 1][ml] = a.y; As[kl + 2][ml] = a.z; As[kl + 3][ml] = a.w;
        Bs[kl + 0][ml] = b.x; Bs[kl + 1][ml] = b.y; Bs[kl + 2][ml] = b.z; Bs[kl + 3][ml] = b.w;
        __syncthreads();
#pragma unroll
        for (int k = 0; k < 16; k++) {
            float4 av = *(const float4*)&As[k][tr * 4];
            float4 bv = *(const float4*)&Bs[k][tc * 4];
            acc[0][0] += av.x * bv.x; acc[0][1] += av.x * bv.y; acc[0][2] += av.x * bv.z; acc[0][3] += av.x * bv.w;
            acc[1][0] += av.y * bv.x; acc[1][1] += av.y * bv.y; acc[1][2] += av.y * bv.z; acc[1][3] += av.y * bv.w;
            acc[2][0] += av.z * bv.x; acc[2][1] += av.z * bv.y; acc[2][2] += av.z * bv.z; acc[2][3] += av.z * bv.w;
            acc[3][0] += av.w * bv.x; acc[3][1] += av.w * bv.y; acc[3][2] += av.w * bv.z; acc[3][3] += av.w * bv.w;
        }
        __syncthreads();
    }

    float4 bv = *(const float4*)&bias[jbase + tc * 4];
#pragma unroll
    for (int i = 0; i < 4; i++) {
        float4 o;
        o.x = acc[i][0] + bv.x;
        o.y = acc[i][1] + bv.y;
        o.z = acc[i][2] + bv.z;
        o.w = acc[i][3] + bv.w;
        *(float4*)&g_xw[(size_t)(m0 + tr * 4 + i) * N4 + n0 + tc * 4] = o;
    }
}

// ---------------------------------------------------------------------------
// Phase 2: persistent kernel, 128 CTAs x 256 threads, all 512 steps.
// CTA tile: 32 batches x 16 hidden units x 4 gates  (=> 32x64 GEMM tile, K=256)
// W slice lives in SMEM for all steps; c-state lives in registers.
// ---------------------------------------------------------------------------
__global__ void __launch_bounds__(256, 1)
qlstm_steps(const float* __restrict__ h0, const float* __restrict__ c0,
            const float* __restrict__ Wf, const float* __restrict__ Wi,
            const float* __restrict__ Wu, const float* __restrict__ Wo,
            const float* __restrict__ thf, const float* __restrict__ scf,
            const float* __restrict__ thi, const float* __restrict__ sci,
            const float* __restrict__ thu, const float* __restrict__ scu,
            const float* __restrict__ tho, const float* __restrict__ sco,
            float* __restrict__ out)
{
    extern __shared__ float smem[];
    float* W_s = smem;                       // [256][64]  (k-major)  64 KB
    float* h_s = smem + 256 * 64;            // [32][256]  (b-major)  32 KB
    float* g_s = smem + 256 * 64 + 32 * 256; // [32][64]   gate stage  8 KB

    const int cid = blockIdx.x;              // 0..127
    const int b0  = (cid & 7) * 32;          // batch tile origin
    const int j0  = (cid >> 3) * 16;         // hidden-unit tile origin

    const int t   = threadIdx.x;
    const int cp  = t & 31;                  // column pair -> cols 2cp, 2cp+1
    const int rg  = t >> 5;                  // row group  -> b_local 4rg..4rg+3
    const int col = 2 * cp;
    const int gsel = col >> 4;               // gate of this thread's 2 columns
    const int jj  = col & 15;

    // ---- preload W slice (h-part, k=256..511) into SMEM: W_s[k][c] ----
    {
        const int c  = t & 63;
        const int kq = (t >> 6) * 64;
        const int gg = c >> 4;
        const float* __restrict__ Wp = (gg == 0) ? Wf : (gg == 1) ? Wi : (gg == 2) ? Wu : Wo;
        const float* src = Wp + (size_t)(j0 + (c & 15)) * 512 + 256 + kq;
#pragma unroll
        for (int q = 0; q < 16; q++) {
            float4 v = *(const float4*)(src + q * 4);
            int kk = kq + q * 4;
            W_s[(kk + 0) * 64 + c] = v.x;
            W_s[(kk + 1) * 64 + c] = v.y;
            W_s[(kk + 2) * 64 + c] = v.z;
            W_s[(kk + 3) * 64 + c] = v.w;
        }
    }

    // ---- per-thread gate constants for its 2 columns ----
    const float* __restrict__ thp = (gsel == 0) ? thf : (gsel == 1) ? thi : (gsel == 2) ? thu : tho;
    const float* __restrict__ scp = (gsel == 0) ? scf : (gsel == 1) ? sci : (gsel == 2) ? scu : sco;
    const float th0 = thp[j0 + jj],     sc0 = scp[j0 + jj];
    const float th1 = thp[j0 + jj + 1], sc1 = scp[j0 + jj + 1];
    // outer nonlinearity: gate u -> tanh(q) = 2*sigmoid(2q)-1 ; others -> sigmoid(q)
    const float va = (gsel == 2) ? 2.0f : 1.0f;
    const float vb = (gsel == 2) ? 2.0f : 1.0f;
    const float vc = (gsel == 2) ? -1.0f : 0.0f;

    const int noff = gsel * 256 + j0 + jj;   // column in XW [.,1024]

    // ---- c-state in registers (update-phase mapping: states s=t and s=t+256) ----
    float c_reg[2];
#pragma unroll
    for (int p = 0; p < 2; p++) {
        int s = t + p * 256;
        c_reg[p] = c0[(size_t)(b0 + (s >> 4)) * 256 + j0 + (s & 15)];
    }

    const int bl = t >> 3;                   // h-slab load: row 0..31
    const int kb = (t & 7) * 4;              // k base 0..28

    for (int ts = 0; ts < SEQ; ts++) {
        // ---- load previous h slab [32 x 256] into SMEM (L2 path, coherent) ----
        const float* hsrc = (ts == 0) ? h0 : (out + (size_t)(ts - 1) * (BATCH * HID));
        {
            const float* hp = hsrc + (size_t)(b0 + bl) * 256 + kb;
#pragma unroll
            for (int q = 0; q < 8; q++) {
                float4 v = __ldcg((const float4*)(hp + q * 32));
                *(float4*)&h_s[bl * 256 + kb + q * 32] = v;
            }
        }
        // prefetch XW contributions for this step
        float2 xwv[4];
        {
            const float* xwp = g_xw + ((size_t)ts * BATCH + b0 + rg * 4) * N4 + noff;
#pragma unroll
            for (int i = 0; i < 4; i++)
                xwv[i] = __ldcg((const float2*)(xwp + (size_t)i * N4));
        }
        __syncthreads();

        // ---- 32x64x256 GEMM tile (fp32) ----
        float acc0[4] = {0.f, 0.f, 0.f, 0.f};
        float acc1[4] = {0.f, 0.f, 0.f, 0.f};
#pragma unroll 4
        for (int k = 0; k < 256; k += 4) {
            float2 w0 = *(const float2*)&W_s[(k + 0) * 64 + col];
            float2 w1 = *(const float2*)&W_s[(k + 1) * 64 + col];
            float2 w2 = *(const float2*)&W_s[(k + 2) * 64 + col];
            float2 w3 = *(const float2*)&W_s[(k + 3) * 64 + col];
#pragma unroll
            for (int i = 0; i < 4; i++) {
                float4 h4 = *(const float4*)&h_s[(rg * 4 + i) * 256 + k];
                acc0[i] += h4.x * w0.x; acc0[i] += h4.y * w1.x;
                acc0[i] += h4.z * w2.x; acc0[i] += h4.w * w3.x;
                acc1[i] += h4.x * w0.y; acc1[i] += h4.y * w1.y;
                acc1[i] += h4.z * w2.y; acc1[i] += h4.w * w3.y;
            }
        }

        // ---- gate nonlinearities -> stage to SMEM ----
#pragma unroll
        for (int i = 0; i < 4; i++) {
            float z0 = acc0[i] + xwv[i].x;
            float z1 = acc1[i] + xwv[i].y;
            float q0 = sigmoidf_(__sinf(z0 * th0) * sc0);
            float q1 = sigmoidf_(__sinf(z1 * th1) * sc1);
            float v0 = va * sigmoidf_(vb * q0) + vc;
            float v1 = va * sigmoidf_(vb * q1) + vc;
            *(float2*)&g_s[(rg * 4 + i) * 64 + col] = make_float2(v0, v1);
        }
        __syncthreads();

        // ---- state update: each thread owns 2 (b,j) states ----
#pragma unroll
        for (int p = 0; p < 2; p++) {
            int s   = t + p * 256;
            int b_u = s >> 4;
            int j_u = s & 15;
            float fv = g_s[b_u * 64 +      j_u];
            float iv = g_s[b_u * 64 + 16 + j_u];
            float uv = g_s[b_u * 64 + 32 + j_u];
            float ov = g_s[b_u * 64 + 48 + j_u];
            float c  = fv * c_reg[p] + iv * uv;
            c_reg[p] = c;
            float h  = ov * tanhf_fast(c);
            size_t oidx = ((size_t)ts * BATCH + (b0 + b_u)) * HID + j0 + j_u;
            out[oidx] = h;
            if (ts == SEQ - 1) {
                size_t sidx = (size_t)(b0 + b_u) * HID + j0 + j_u;
                out[OUT_SEQ_ELEMS + sidx] = h;                    // h_n
                out[OUT_SEQ_ELEMS + (size_t)BATCH * HID + sidx] = c; // c_n
            }
        }

        if (ts < SEQ - 1) grid_barrier(gridDim.x);
    }
}

// ---------------------------------------------------------------------------
extern "C" void kernel_launch(void* const* d_in, const int* in_sizes, int n_in,
                              void* d_out, int out_size)
{
    (void)in_sizes; (void)n_in; (void)out_size;
    const float* inputs = (const float*)d_in[0];
    const float* h0  = (const float*)d_in[1];
    const float* c0  = (const float*)d_in[2];
    const float* Wf  = (const float*)d_in[3];
    const float* bf  = (const float*)d_in[4];
    const float* thf = (const float*)d_in[5];
    const float* scf = (const float*)d_in[6];
    const float* Wi  = (const float*)d_in[7];
    const float* bi  = (const float*)d_in[8];
    const float* thi = (const float*)d_in[9];
    const float* sci = (const float*)d_in[10];
    const float* Wu  = (const float*)d_in[11];
    const float* bu  = (const float*)d_in[12];
    const float* thu = (const float*)d_in[13];
    const float* scu = (const float*)d_in[14];
    const float* Wo  = (const float*)d_in[15];
    const float* bo  = (const float*)d_in[16];
    const float* tho = (const float*)d_in[17];
    const float* sco = (const float*)d_in[18];
    float* out = (float*)d_out;

    dim3 g1(16, (SEQ * BATCH) / 64);   // (16, 2048)
    xw_gemm<<<g1, 256>>>(inputs, Wf, Wi, Wu, Wo, bf, bi, bu, bo);

    const int smem_bytes = (256 * 64 + 32 * 256 + 32 * 64) * (int)sizeof(float); // 106496
    cudaFuncSetAttribute(qlstm_steps, cudaFuncAttributeMaxDynamicSharedMemorySize, smem_bytes);
    qlstm_steps<<<128, 256, smem_bytes>>>(h0, c0, Wf, Wi, Wu, Wo,
                                          thf, scf, thi, sci, thu, scu, tho, sco,
                                          out);
}

// round 3
// speedup vs baseline: 1.2162x; 1.2162x over previous
#include <cuda_runtime.h>
#include <cuda_bf16.h>
#include <cstdint>

#define SEQ 512
#define BATCH 256
#define HID 256
#define N4 1024
#define GM_M (SEQ * BATCH)                           // 131072 rows
#define OUT_SEQ_ELEMS ((size_t)SEQ * BATCH * HID)    // 33554432

// scratch
__device__ float g_xw[(size_t)SEQ * BATCH * N4];                 // 512 MB
__device__ __nv_bfloat16 g_axhi[(size_t)GM_M * 256];             // 67 MB
__device__ __nv_bfloat16 g_axlo[(size_t)GM_M * 256];             // 67 MB
__device__ __nv_bfloat16 g_wxhi[1024 * 256];
__device__ __nv_bfloat16 g_wxlo[1024 * 256];
__device__ unsigned long long g_bar_counter = 0ULL;

// ---------------------------------------------------------------------------
// helpers
// ---------------------------------------------------------------------------
__device__ __forceinline__ float sigmoidf_(float x) {
    return __fdividef(1.0f, 1.0f + __expf(-x));
}
__device__ __forceinline__ float tanhf_fast(float x) {
    return 2.0f * sigmoidf_(2.0f * x) - 1.0f;
}
__device__ __forceinline__ unsigned long long fma2_(unsigned long long a,
                                                    unsigned long long b,
                                                    unsigned long long c) {
    unsigned long long d;
    asm("fma.rn.f32x2 %0, %1, %2, %3;" : "=l"(d) : "l"(a), "l"(b), "l"(c));
    return d;
}
__device__ __forceinline__ float2 unpack2_(unsigned long long a) {
    float2 f;
    asm("mov.b64 {%0, %1}, %2;" : "=f"(f.x), "=f"(f.y) : "l"(a));
    return f;
}
__device__ __forceinline__ void grid_barrier(unsigned nblocks) {
    __threadfence();
    __syncthreads();
    if (threadIdx.x == 0) {
        unsigned long long ticket = atomicAdd(&g_bar_counter, 1ULL);
        unsigned long long target = (ticket / nblocks + 1ULL) * (unsigned long long)nblocks;
        while (*((volatile unsigned long long*)&g_bar_counter) < target) {
            __nanosleep(32);
        }
    }
    __syncthreads();
}

// legacy tensor-core mma (compute_80 PTX — compiles under compute_103)
__device__ __forceinline__ void mma16816(float* c, const uint32_t* a, const uint32_t* b) {
    asm volatile(
        "mma.sync.aligned.m16n8k16.row.col.f32.bf16.bf16.f32 "
        "{%0,%1,%2,%3}, {%4,%5,%6,%7}, {%8,%9}, {%0,%1,%2,%3};"
        : "+f"(c[0]), "+f"(c[1]), "+f"(c[2]), "+f"(c[3])
        : "r"(a[0]), "r"(a[1]), "r"(a[2]), "r"(a[3]), "r"(b[0]), "r"(b[1]));
}

// ---------------------------------------------------------------------------
// converts: fp32 -> (hi, lo) bf16 planes, row-major [row][256]
// ---------------------------------------------------------------------------
__global__ void __launch_bounds__(256)
conv_x(const float* __restrict__ X) {
    size_t i = (size_t)blockIdx.x * 256 + threadIdx.x;   // float4 index
    float4 v = ((const float4*)X)[i];
    float f[4] = {v.x, v.y, v.z, v.w};
    __nv_bfloat16 h[4], l[4];
#pragma unroll
    for (int j = 0; j < 4; j++) {
        h[j] = __float2bfloat16(f[j]);
        l[j] = __float2bfloat16(f[j] - __bfloat162float(h[j]));
    }
    ((__nv_bfloat162*)g_axhi)[2 * i]     = __nv_bfloat162(h[0], h[1]);
    ((__nv_bfloat162*)g_axhi)[2 * i + 1] = __nv_bfloat162(h[2], h[3]);
    ((__nv_bfloat162*)g_axlo)[2 * i]     = __nv_bfloat162(l[0], l[1]);
    ((__nv_bfloat162*)g_axlo)[2 * i + 1] = __nv_bfloat162(l[2], l[3]);
}

__global__ void __launch_bounds__(256)
conv_w(const float* __restrict__ Wf, const float* __restrict__ Wi,
       const float* __restrict__ Wu, const float* __restrict__ Wo) {
    int e = blockIdx.x * 256 + threadIdx.x;   // float4 index, 65536 total
    int n = e >> 6;
    int kq = (e & 63) * 4;
    int g = n >> 8, j = n & 255;
    const float* Wp = (g == 0) ? Wf : (g == 1) ? Wi : (g == 2) ? Wu : Wo;
    float4 v = *(const float4*)(Wp + (size_t)j * 512 + kq);
    float f[4] = {v.x, v.y, v.z, v.w};
    __nv_bfloat16 h[4], l[4];
#pragma unroll
    for (int q = 0; q < 4; q++) {
        h[q] = __float2bfloat16(f[q]);
        l[q] = __float2bfloat16(f[q] - __bfloat162float(h[q]));
    }
    size_t o = (size_t)n * 256 + kq;
    ((__nv_bfloat162*)(g_wxhi + o))[0] = __nv_bfloat162(h[0], h[1]);
    ((__nv_bfloat162*)(g_wxhi + o))[1] = __nv_bfloat162(h[2], h[3]);
    ((__nv_bfloat162*)(g_wxlo + o))[0] = __nv_bfloat162(l[0], l[1]);
    ((__nv_bfloat162*)(g_wxlo + o))[1] = __nv_bfloat162(l[2], l[3]);
}

// ---------------------------------------------------------------------------
// Phase 1: XW = X @ Wx^T + b  via mma.sync bf16 3-product split.
// grid (8 n-tiles, 1024 m-tiles), 256 threads. CTA tile 128m x 128n, K=256.
// SMEM holds fragments in fragment-major order (conflict-free lane loads).
// ---------------------------------------------------------------------------
__global__ void __launch_bounds__(256, 1)
xw_mma(const float* __restrict__ bfb, const float* __restrict__ bib,
       const float* __restrict__ bub, const float* __restrict__ bob)
{
    __shared__ uint32_t A_hi[2048], A_lo[2048];   // [ks2][mt8][lane32][reg4]
    __shared__ uint32_t B_hi[2048], B_lo[2048];   // [ks2][nf16][lane32][reg2]

    const int t = threadIdx.x;
    const int lane = t & 31, wid = t >> 5;
    const int bx = blockIdx.x;                    // n-tile 0..7
    const int m0 = blockIdx.y * 128;
    const int n0 = bx * 128;
    const int wm = wid & 3;                       // warp m-offset: 32*wm
    const int wn = wid >> 1 & 1;                  // placeholder (fixed below)

    const int wnn = wid >> 2;                     // warp n-offset: 64*wnn  (wid 0..7 -> 4x2)

    float c[2][8][4];
#pragma unroll
    for (int i = 0; i < 2; i++)
#pragma unroll
        for (int j = 0; j < 8; j++)
#pragma unroll
            for (int q = 0; q < 4; q++) c[i][j][q] = 0.0f;

    const uint32_t* __restrict__ Axh = (const uint32_t*)g_axhi;  // [m][128 words]
    const uint32_t* __restrict__ Axl = (const uint32_t*)g_axlo;
    const uint32_t* __restrict__ Bwh = (const uint32_t*)g_wxhi;  // [n][128 words]
    const uint32_t* __restrict__ Bwl = (const uint32_t*)g_wxlo;

    for (int kc = 0; kc < 256; kc += 32) {
        __syncthreads();
        // ---- A scatter: 128m x 16kp words ----
#pragma unroll
        for (int q = 0; q < 2; q++) {
            int iw4 = t + q * 256;                 // uint4 index, 512 total
            int m = iw4 >> 2, kpb = (iw4 & 3) * 4;
            size_t gi = (size_t)(m0 + m) * 128 + (kc >> 1) + kpb;
            uint4 vh = *(const uint4*)(Axh + gi);
            uint4 vl = *(const uint4*)(Axl + gi);
            const uint32_t* ph = (const uint32_t*)&vh;
            const uint32_t* pl = (const uint32_t*)&vl;
#pragma unroll
            for (int j = 0; j < 4; j++) {
                int klocal = (kpb + j) * 2;
                int ks = klocal >> 4, kk = klocal & 15;
                int mt = m >> 4, r = m & 15;
                int ln = (r & 7) * 4 + ((kk & 7) >> 1);
                int rg = (r >> 3) | ((kk >> 3) << 1);
                int idx = ((ks * 8 + mt) * 32 + ln) * 4 + rg;
                A_hi[idx] = ph[j];
                A_lo[idx] = pl[j];
            }
        }
        // ---- B scatter: 128n x 16kp words ----
#pragma unroll
        for (int q = 0; q < 2; q++) {
            int iw4 = t + q * 256;
            int n = iw4 >> 2, kpb = (iw4 & 3) * 4;
            size_t gi = (size_t)(n0 + n) * 128 + (kc >> 1) + kpb;
            uint4 vh = *(const uint4*)(Bwh + gi);
            uint4 vl = *(const uint4*)(Bwl + gi);
            const uint32_t* ph = (const uint32_t*)&vh;
            const uint32_t* pl = (const uint32_t*)&vl;
#pragma unroll
            for (int j = 0; j < 4; j++) {
                int klocal = (kpb + j) * 2;
                int ks = klocal >> 4, kk = klocal & 15;
                int nf = n >> 3;
                int ln = (n & 7) * 4 + ((kk & 7) >> 1);
                int rg = kk >> 3;
                int idx = ((ks * 16 + nf) * 32 + ln) * 2 + rg;
                B_hi[idx] = ph[j];
                B_lo[idx] = pl[j];
            }
        }
        __syncthreads();

        // ---- compute: 2 k-steps of 16 ----
#pragma unroll
        for (int ks = 0; ks < 2; ks++) {
            uint32_t ah[2][4], al[2][4];
#pragma unroll
            for (int mt2 = 0; mt2 < 2; mt2++) {
                int abase = ((ks * 8 + wm * 2 + mt2) * 32 + lane) * 4;
                *(uint4*)ah[mt2] = *(const uint4*)&A_hi[abase];
                *(uint4*)al[mt2] = *(const uint4*)&A_lo[abase];
            }
#pragma unroll
            for (int nf2 = 0; nf2 < 8; nf2++) {
                int nf = wnn * 8 + nf2;
                int bbase = ((ks * 16 + nf) * 32 + lane) * 2;
                uint32_t bh[2], bl[2];
                *(uint2*)bh = *(const uint2*)&B_hi[bbase];
                *(uint2*)bl = *(const uint2*)&B_lo[bbase];
#pragma unroll
                for (int mt2 = 0; mt2 < 2; mt2++) {
                    mma16816(c[mt2][nf2], ah[mt2], bh);   // hi*hi
                    mma16816(c[mt2][nf2], ah[mt2], bl);   // hi*lo
                    mma16816(c[mt2][nf2], al[mt2], bh);   // lo*hi
                }
            }
        }
    }

    // ---- epilogue: add bias, store fp32 ----
    const int gate = bx >> 1;
    const float* __restrict__ bias =
        (gate == 0) ? bfb : (gate == 1) ? bib : (gate == 2) ? bub : bob;
    const int jb = (bx & 1) * 128;
#pragma unroll
    for (int mt2 = 0; mt2 < 2; mt2++) {
#pragma unroll
        for (int nf2 = 0; nf2 < 8; nf2++) {
            int row0 = wm * 32 + mt2 * 16 + (lane >> 2);
            int col0 = wnn * 64 + nf2 * 8 + (lane & 3) * 2;
            float b0 = __ldg(&bias[jb + col0]);
            float b1 = __ldg(&bias[jb + col0 + 1]);
            size_t base = (size_t)(m0 + row0) * N4 + n0 + col0;
            *(float2*)&g_xw[base] =
                make_float2(c[mt2][nf2][0] + b0, c[mt2][nf2][1] + b1);
            *(float2*)&g_xw[base + 8 * N4] =
                make_float2(c[mt2][nf2][2] + b0, c[mt2][nf2][3] + b1);
        }
    }
    (void)wn;
}

// ---------------------------------------------------------------------------
// Phase 2: persistent, 128 CTAs x 128 threads, fma.rn.f32x2 recurrent GEMM.
// CTA tile: 32 batches x 16 j x 4 gates. thread: 8 rows x 2 cols.
// ---------------------------------------------------------------------------
__global__ void __launch_bounds__(128, 1)
qlstm_steps(const float* __restrict__ h0, const float* __restrict__ c0,
            const float* __restrict__ Wf, const float* __restrict__ Wi,
            const float* __restrict__ Wu, const float* __restrict__ Wo,
            const float* __restrict__ thf, const float* __restrict__ scf,
            const float* __restrict__ thi, const float* __restrict__ sci,
            const float* __restrict__ thu, const float* __restrict__ scu,
            const float* __restrict__ tho, const float* __restrict__ sco,
            float* __restrict__ out)
{
    extern __shared__ float sm2[];
    float* W_s2 = sm2;                      // k-pair interleaved, 64 KB
    float* h_s  = sm2 + 16384;              // [32][256] 32 KB
    float* g_s  = sm2 + 16384 + 8192;       // [32][64]   8 KB

    const int cid = blockIdx.x;
    const int b0  = (cid & 7) * 32;
    const int j0  = (cid >> 3) * 16;

    const int t   = threadIdx.x;            // 0..127
    const int cp  = t & 31;
    const int rg  = t >> 5;                 // rows rg*8..rg*8+7
    const int col = 2 * cp;
    const int gsel = col >> 4;
    const int jj  = col & 15;

    // W preload: W_s2[(k>>1)*128 + 2c + (k&1)] = W[j0 + (c&15)][256+k]
    {
        const int c  = t & 63;
        const int kh = (t >> 6) * 128;
        const int gg = c >> 4;
        const float* __restrict__ Wp = (gg == 0) ? Wf : (gg == 1) ? Wi : (gg == 2) ? Wu : Wo;
        const float* src = Wp + (size_t)(j0 + (c & 15)) * 512 + 256 + kh;
#pragma unroll
        for (int q = 0; q < 32; q++) {
            float4 v = *(const float4*)(src + q * 4);
            int k = kh + q * 4;
            int base = (k >> 1) * 128 + 2 * c;
            W_s2[base]       = v.x;
            W_s2[base + 1]   = v.y;
            W_s2[base + 128] = v.z;
            W_s2[base + 129] = v.w;
        }
    }

    const float* __restrict__ thp = (gsel == 0) ? thf : (gsel == 1) ? thi : (gsel == 2) ? thu : tho;
    const float* __restrict__ scp = (gsel == 0) ? scf : (gsel == 1) ? sci : (gsel == 2) ? scu : sco;
    const float th0 = thp[j0 + jj],     sc0 = scp[j0 + jj];
    const float th1 = thp[j0 + jj + 1], sc1 = scp[j0 + jj + 1];
    const float va = (gsel == 2) ? 2.0f : 1.0f;
    const float vb = (gsel == 2) ? 2.0f : 1.0f;
    const float vc = (gsel == 2) ? -1.0f : 0.0f;
    const int noff = gsel * 256 + j0 + jj;

    float c_reg[4];
#pragma unroll
    for (int p = 0; p < 4; p++) {
        int s = t + p * 128;
        c_reg[p] = c0[(size_t)(b0 + (s >> 4)) * 256 + j0 + (s & 15)];
    }

    for (int ts = 0; ts < SEQ; ts++) {
        const float* hsrc = (ts == 0) ? h0 : (out + (size_t)(ts - 1) * (BATCH * HID));
#pragma unroll
        for (int q = 0; q < 16; q++) {
            int i = t + q * 128;
            int row = i >> 6, kq = (i & 63) * 4;
            float4 v = __ldcg((const float4*)(hsrc + (size_t)(b0 + row) * 256 + kq));
            *(float4*)&h_s[row * 256 + kq] = v;
        }
        float2 xwv[8];
        {
            const float* xwp = g_xw + ((size_t)ts * BATCH + b0 + rg * 8) * N4 + noff;
#pragma unroll
            for (int i = 0; i < 8; i++)
                xwv[i] = __ldcg((const float2*)(xwp + (size_t)i * N4));
        }
        __syncthreads();

        unsigned long long acc[8][2];
#pragma unroll
        for (int i = 0; i < 8; i++) { acc[i][0] = 0ULL; acc[i][1] = 0ULL; }

#pragma unroll 4
        for (int k = 0; k < 256; k += 4) {
            ulonglong2 w01 = *(const ulonglong2*)&W_s2[(k >> 1) * 128 + 4 * cp];
            ulonglong2 w23 = *(const ulonglong2*)&W_s2[(k >> 1) * 128 + 128 + 4 * cp];
#pragma unroll
            for (int i = 0; i < 8; i++) {
                ulonglong2 h2 = *(const ulonglong2*)&h_s[(rg * 8 + i) * 256 + k];
                acc[i][0] = fma2_(h2.x, w01.x, acc[i][0]);
                acc[i][1] = fma2_(h2.x, w01.y, acc[i][1]);
                acc[i][0] = fma2_(h2.y, w23.x, acc[i][0]);
                acc[i][1] = fma2_(h2.y, w23.y, acc[i][1]);
            }
        }

#pragma unroll
        for (int i = 0; i < 8; i++) {
            float2 a0 = unpack2_(acc[i][0]);
            float2 a1 = unpack2_(acc[i][1]);
            float z0 = a0.x + a0.y + xwv[i].x;
            float z1 = a1.x + a1.y + xwv[i].y;
            float q0 = sigmoidf_(__sinf(z0 * th0) * sc0);
            float q1 = sigmoidf_(__sinf(z1 * th1) * sc1);
            float v0 = va * sigmoidf_(vb * q0) + vc;
            float v1 = va * sigmoidf_(vb * q1) + vc;
            *(float2*)&g_s[(rg * 8 + i) * 64 + col] = make_float2(v0, v1);
        }
        __syncthreads();

#pragma unroll
        for (int p = 0; p < 4; p++) {
            int s   = t + p * 128;
            int b_u = s >> 4;
            int j_u = s & 15;
            float fv = g_s[b_u * 64 +      j_u];
            float iv = g_s[b_u * 64 + 16 + j_u];
            float uv = g_s[b_u * 64 + 32 + j_u];
            float ov = g_s[b_u * 64 + 48 + j_u];
            float cc = fv * c_reg[p] + iv * uv;
            c_reg[p] = cc;
            float h  = ov * tanhf_fast(cc);
            size_t oidx = ((size_t)ts * BATCH + (b0 + b_u)) * HID + j0 + j_u;
            out[oidx] = h;
            if (ts == SEQ - 1) {
                size_t sidx = (size_t)(b0 + b_u) * HID + j0 + j_u;
                out[OUT_SEQ_ELEMS + sidx] = h;
                out[OUT_SEQ_ELEMS + (size_t)BATCH * HID + sidx] = cc;
            }
        }

        if (ts < SEQ - 1) grid_barrier(gridDim.x);
    }
}

// ---------------------------------------------------------------------------
extern "C" void kernel_launch(void* const* d_in, const int* in_sizes, int n_in,
                              void* d_out, int out_size)
{
    (void)in_sizes; (void)n_in; (void)out_size;
    const float* inputs = (const float*)d_in[0];
    const float* h0  = (const float*)d_in[1];
    const float* c0  = (const float*)d_in[2];
    const float* Wf  = (const float*)d_in[3];
    const float* bf  = (const float*)d_in[4];
    const float* thf = (const float*)d_in[5];
    const float* scf = (const float*)d_in[6];
    const float* Wi  = (const float*)d_in[7];
    const float* bi  = (const float*)d_in[8];
    const float* thi = (const float*)d_in[9];
    const float* sci = (const float*)d_in[10];
    const float* Wu  = (const float*)d_in[11];
    const float* bu  = (const float*)d_in[12];
    const float* thu = (const float*)d_in[13];
    const float* scu = (const float*)d_in[14];
    const float* Wo  = (const float*)d_in[15];
    const float* bo  = (const float*)d_in[16];
    const float* tho = (const float*)d_in[17];
    const float* sco = (const float*)d_in[18];
    float* out = (float*)d_out;

    // convert splits
    conv_x<<<(GM_M * 256) / (256 * 4), 256>>>(inputs);
    conv_w<<<(1024 * 256) / (256 * 4), 256>>>(Wf, Wi, Wu, Wo);

    // phase 1: tensor-core x@Wx^T + b  (legacy mma.sync path)
    dim3 g1(8, GM_M / 128);
    xw_mma<<<g1, 256>>>(bf, bi, bu, bo);

    // phase 2: recurrent steps
    const int smem2 = (16384 + 8192 + 2048) * (int)sizeof(float); // 106496
    cudaFuncSetAttribute(qlstm_steps, cudaFuncAttributeMaxDynamicSharedMemorySize, smem2);
    qlstm_steps<<<128, 128, smem2>>>(h0, c0, Wf, Wi, Wu, Wo,
                                     thf, scf, thi, sci, thu, scu, tho, sco,
                                     out);
}

// round 4
// speedup vs baseline: 1.6479x; 1.3550x over previous
#include <cuda_runtime.h>
#include <cuda_bf16.h>
#include <cstdint>

#define SEQ 512
#define BATCH 256
#define HID 256
#define N4 1024
#define GM_M (SEQ * BATCH)                           // 131072 rows
#define OUT_SEQ_ELEMS ((size_t)SEQ * BATCH * HID)    // 33554432

// scratch
__device__ float g_xw[(size_t)SEQ * BATCH * N4];                 // 512 MB
__device__ __nv_bfloat16 g_axhi[(size_t)GM_M * 256];             // 67 MB
__device__ __nv_bfloat16 g_axlo[(size_t)GM_M * 256];             // 67 MB
__device__ __nv_bfloat16 g_wxhi[1024 * 256];
__device__ __nv_bfloat16 g_wxlo[1024 * 256];

// h fragment buffers: [parity][bg][ (ks*32 + lane)*4 + reg ] uint32 (2 bf16)
#define FRAG_WORDS (16 * 32 * 4)
__device__ uint32_t g_hfhi[2][16][FRAG_WORDS];
__device__ uint32_t g_hflo[2][16][FRAG_WORDS];
// per-group barrier counters, padded 128B apart
__device__ unsigned long long g_gbar[16 * 16];

// ---------------------------------------------------------------------------
// helpers
// ---------------------------------------------------------------------------
__device__ __forceinline__ float sigmoidf_(float x) {
    return __fdividef(1.0f, 1.0f + __expf(-x));
}
__device__ __forceinline__ float tanhf_fast(float x) {
    return 2.0f * sigmoidf_(2.0f * x) - 1.0f;
}

// legacy tensor-core mma (compute_80 PTX — compiles under compute_103)
__device__ __forceinline__ void mma16816(float* c, const uint32_t* a, const uint32_t* b) {
    asm volatile(
        "mma.sync.aligned.m16n8k16.row.col.f32.bf16.bf16.f32 "
        "{%0,%1,%2,%3}, {%4,%5,%6,%7}, {%8,%9}, {%0,%1,%2,%3};"
        : "+f"(c[0]), "+f"(c[1]), "+f"(c[2]), "+f"(c[3])
        : "r"(a[0]), "r"(a[1]), "r"(a[2]), "r"(a[3]), "r"(b[0]), "r"(b[1]));
}

__device__ __forceinline__ void group_barrier(int bg) {
    __threadfence();
    __syncthreads();
    if (threadIdx.x == 0) {
        unsigned long long* ctr = &g_gbar[bg * 16];
        unsigned long long ticket = atomicAdd(ctr, 1ULL);
        unsigned long long target = (ticket / 8ULL + 1ULL) * 8ULL;
        while (*((volatile unsigned long long*)ctr) < target) {}
    }
    __syncthreads();
}

// ---------------------------------------------------------------------------
// converts: fp32 -> (hi, lo) bf16 planes, row-major [row][256]
// ---------------------------------------------------------------------------
__global__ void __launch_bounds__(256)
conv_x(const float* __restrict__ X) {
    size_t i = (size_t)blockIdx.x * 256 + threadIdx.x;   // float4 index
    float4 v = ((const float4*)X)[i];
    float f[4] = {v.x, v.y, v.z, v.w};
    __nv_bfloat16 h[4], l[4];
#pragma unroll
    for (int j = 0; j < 4; j++) {
        h[j] = __float2bfloat16(f[j]);
        l[j] = __float2bfloat16(f[j] - __bfloat162float(h[j]));
    }
    ((__nv_bfloat162*)g_axhi)[2 * i]     = __nv_bfloat162(h[0], h[1]);
    ((__nv_bfloat162*)g_axhi)[2 * i + 1] = __nv_bfloat162(h[2], h[3]);
    ((__nv_bfloat162*)g_axlo)[2 * i]     = __nv_bfloat162(l[0], l[1]);
    ((__nv_bfloat162*)g_axlo)[2 * i + 1] = __nv_bfloat162(l[2], l[3]);
}

__global__ void __launch_bounds__(256)
conv_w(const float* __restrict__ Wf, const float* __restrict__ Wi,
       const float* __restrict__ Wu, const float* __restrict__ Wo) {
    int e = blockIdx.x * 256 + threadIdx.x;   // float4 index, 65536 total
    int n = e >> 6;
    int kq = (e & 63) * 4;
    int g = n >> 8, j = n & 255;
    const float* Wp = (g == 0) ? Wf : (g == 1) ? Wi : (g == 2) ? Wu : Wo;
    float4 v = *(const float4*)(Wp + (size_t)j * 512 + kq);
    float f[4] = {v.x, v.y, v.z, v.w};
    __nv_bfloat16 h[4], l[4];
#pragma unroll
    for (int q = 0; q < 4; q++) {
        h[q] = __float2bfloat16(f[q]);
        l[q] = __float2bfloat16(f[q] - __bfloat162float(h[q]));
    }
    size_t o = (size_t)n * 256 + kq;
    ((__nv_bfloat162*)(g_wxhi + o))[0] = __nv_bfloat162(h[0], h[1]);
    ((__nv_bfloat162*)(g_wxhi + o))[1] = __nv_bfloat162(h[2], h[3]);
    ((__nv_bfloat162*)(g_wxlo + o))[0] = __nv_bfloat162(l[0], l[1]);
    ((__nv_bfloat162*)(g_wxlo + o))[1] = __nv_bfloat162(l[2], l[3]);
}

// h0 -> fragment buffer parity 0
__global__ void __launch_bounds__(256)
conv_h0(const float* __restrict__ h0) {
    int idx = blockIdx.x * 256 + threadIdx.x;    // 65536
    int b = idx >> 8, j = idx & 255;
    float v = h0[idx];
    __nv_bfloat16 hh = __float2bfloat16(v);
    __nv_bfloat16 hl = __float2bfloat16(v - __bfloat162float(hh));
    int bg = b >> 4, b_l = b & 15;
    int ks = j >> 4, kk = j & 15;
    int lp = (b_l & 7) * 4 + ((kk & 7) >> 1);
    int reg = ((b_l >> 3) & 1) | ((kk >> 3) << 1);
    int fi = (ks * 32 + lp) * 4 + reg;
    ((__nv_bfloat16*)&g_hfhi[0][bg][fi])[kk & 1] = hh;
    ((__nv_bfloat16*)&g_hflo[0][bg][fi])[kk & 1] = hl;
}

// ---------------------------------------------------------------------------
// Phase 1: XW = X @ Wx^T + b  via mma.sync bf16 3-product split. (unchanged R3)
// ---------------------------------------------------------------------------
__global__ void __launch_bounds__(256, 1)
xw_mma(const float* __restrict__ bfb, const float* __restrict__ bib,
       const float* __restrict__ bub, const float* __restrict__ bob)
{
    __shared__ uint32_t A_hi[2048], A_lo[2048];
    __shared__ uint32_t B_hi[2048], B_lo[2048];

    const int t = threadIdx.x;
    const int lane = t & 31, wid = t >> 5;
    const int bx = blockIdx.x;
    const int m0 = blockIdx.y * 128;
    const int n0 = bx * 128;
    const int wm = wid & 3;
    const int wnn = wid >> 2;

    float c[2][8][4];
#pragma unroll
    for (int i = 0; i < 2; i++)
#pragma unroll
        for (int j = 0; j < 8; j++)
#pragma unroll
            for (int q = 0; q < 4; q++) c[i][j][q] = 0.0f;

    const uint32_t* __restrict__ Axh = (const uint32_t*)g_axhi;
    const uint32_t* __restrict__ Axl = (const uint32_t*)g_axlo;
    const uint32_t* __restrict__ Bwh = (const uint32_t*)g_wxhi;
    const uint32_t* __restrict__ Bwl = (const uint32_t*)g_wxlo;

    for (int kc = 0; kc < 256; kc += 32) {
        __syncthreads();
#pragma unroll
        for (int q = 0; q < 2; q++) {
            int iw4 = t + q * 256;
            int m = iw4 >> 2, kpb = (iw4 & 3) * 4;
            size_t gi = (size_t)(m0 + m) * 128 + (kc >> 1) + kpb;
            uint4 vh = *(const uint4*)(Axh + gi);
            uint4 vl = *(const uint4*)(Axl + gi);
            const uint32_t* ph = (const uint32_t*)&vh;
            const uint32_t* pl = (const uint32_t*)&vl;
#pragma unroll
            for (int j = 0; j < 4; j++) {
                int klocal = (kpb + j) * 2;
                int ks = klocal >> 4, kk = klocal & 15;
                int mt = m >> 4, r = m & 15;
                int ln = (r & 7) * 4 + ((kk & 7) >> 1);
                int rg = (r >> 3) | ((kk >> 3) << 1);
                int idx = ((ks * 8 + mt) * 32 + ln) * 4 + rg;
                A_hi[idx] = ph[j];
                A_lo[idx] = pl[j];
            }
        }
#pragma unroll
        for (int q = 0; q < 2; q++) {
            int iw4 = t + q * 256;
            int n = iw4 >> 2, kpb = (iw4 & 3) * 4;
            size_t gi = (size_t)(n0 + n) * 128 + (kc >> 1) + kpb;
            uint4 vh = *(const uint4*)(Bwh + gi);
            uint4 vl = *(const uint4*)(Bwl + gi);
            const uint32_t* ph = (const uint32_t*)&vh;
            const uint32_t* pl = (const uint32_t*)&vl;
#pragma unroll
            for (int j = 0; j < 4; j++) {
                int klocal = (kpb + j) * 2;
                int ks = klocal >> 4, kk = klocal & 15;
                int nf = n >> 3;
                int ln = (n & 7) * 4 + ((kk & 7) >> 1);
                int rg = kk >> 3;
                int idx = ((ks * 16 + nf) * 32 + ln) * 2 + rg;
                B_hi[idx] = ph[j];
                B_lo[idx] = pl[j];
            }
        }
        __syncthreads();

#pragma unroll
        for (int ks = 0; ks < 2; ks++) {
            uint32_t ah[2][4], al[2][4];
#pragma unroll
            for (int mt2 = 0; mt2 < 2; mt2++) {
                int abase = ((ks * 8 + wm * 2 + mt2) * 32 + lane) * 4;
                *(uint4*)ah[mt2] = *(const uint4*)&A_hi[abase];
                *(uint4*)al[mt2] = *(const uint4*)&A_lo[abase];
            }
#pragma unroll
            for (int nf2 = 0; nf2 < 8; nf2++) {
                int nf = wnn * 8 + nf2;
                int bbase = ((ks * 16 + nf) * 32 + lane) * 2;
                uint32_t bh[2], bl[2];
                *(uint2*)bh = *(const uint2*)&B_hi[bbase];
                *(uint2*)bl = *(const uint2*)&B_lo[bbase];
#pragma unroll
                for (int mt2 = 0; mt2 < 2; mt2++) {
                    mma16816(c[mt2][nf2], ah[mt2], bh);
                    mma16816(c[mt2][nf2], ah[mt2], bl);
                    mma16816(c[mt2][nf2], al[mt2], bh);
                }
            }
        }
    }

    const int gate = bx >> 1;
    const float* __restrict__ bias =
        (gate == 0) ? bfb : (gate == 1) ? bib : (gate == 2) ? bub : bob;
    const int jb = (bx & 1) * 128;
#pragma unroll
    for (int mt2 = 0; mt2 < 2; mt2++) {
#pragma unroll
        for (int nf2 = 0; nf2 < 8; nf2++) {
            int row0 = wm * 32 + mt2 * 16 + (lane >> 2);
            int col0 = wnn * 64 + nf2 * 8 + (lane & 3) * 2;
            float b0 = __ldg(&bias[jb + col0]);
            float b1 = __ldg(&bias[jb + col0 + 1]);
            size_t base = (size_t)(m0 + row0) * N4 + n0 + col0;
            *(float2*)&g_xw[base] =
                make_float2(c[mt2][nf2][0] + b0, c[mt2][nf2][1] + b1);
            *(float2*)&g_xw[base + 8 * N4] =
                make_float2(c[mt2][nf2][2] + b0, c[mt2][nf2][3] + b1);
        }
    }
}

// ---------------------------------------------------------------------------
// Phase 2: persistent, 128 CTAs x 256 threads, tensor-core recurrent GEMM.
// CTA: 16 batches (bg = cid>>3) x 32 j x 4 gates (jt = cid&7). K = 256.
// A-frags (h) read directly from gmem frag buffers; B-frags (W) in SMEM.
// ---------------------------------------------------------------------------
__global__ void __launch_bounds__(256, 1)
qlstm_steps(const float* __restrict__ c0,
            const float* __restrict__ Wf, const float* __restrict__ Wi,
            const float* __restrict__ Wu, const float* __restrict__ Wo,
            const float* __restrict__ thf, const float* __restrict__ scf,
            const float* __restrict__ thi, const float* __restrict__ sci,
            const float* __restrict__ thu, const float* __restrict__ scu,
            const float* __restrict__ tho, const float* __restrict__ sco,
            float* __restrict__ out)
{
    extern __shared__ char smraw[];
    uint32_t* Bf_hi = (uint32_t*)smraw;            // [16ks][16nf][32][2] = 64 KB
    uint32_t* Bf_lo = Bf_hi + 16384;               // 64 KB
    float* g_s = (float*)(Bf_lo + 16384);          // [16][132] pad

    const int cid = blockIdx.x;
    const int bg  = cid >> 3;                      // 0..15 batch group (16 b)
    const int jt  = cid & 7;                       // 0..7 j tile (32 j)
    const int j0  = jt * 32;

    const int t = threadIdx.x;
    const int lane = t & 31, w = t >> 5;           // 8 warps
    const int gate = w >> 1;

    // ---- W -> fragment-major bf16 hi/lo in SMEM (one-time) ----
    {
        const int c = t >> 1;                      // col 0..127
        const int kb = (t & 1) * 128;              // k half
        const int gg = c >> 5;
        const float* __restrict__ Wp = (gg == 0) ? Wf : (gg == 1) ? Wi
                                       : (gg == 2) ? Wu : Wo;
        const float* src = Wp + (size_t)(j0 + (c & 31)) * 512 + 256 + kb;
        const int nf = c >> 3;
        const int lp_base = (c & 7) * 4;
#pragma unroll 8
        for (int q = 0; q < 32; q++) {
            float4 v = *(const float4*)(src + q * 4);
            float f[4] = {v.x, v.y, v.z, v.w};
#pragma unroll
            for (int e = 0; e < 4; e++) {
                int k = kb + q * 4 + e;
                int ks = k >> 4, kk = k & 15;
                int lp = lp_base + ((kk & 7) >> 1);
                int rg = kk >> 3;
                int fi = ((ks * 16 + nf) * 32 + lp) * 2 + rg;
                __nv_bfloat16 hh = __float2bfloat16(f[e]);
                __nv_bfloat16 hl = __float2bfloat16(f[e] - __bfloat162float(hh));
                ((__nv_bfloat16*)&Bf_hi[fi])[kk & 1] = hh;
                ((__nv_bfloat16*)&Bf_lo[fi])[kk & 1] = hl;
            }
        }
    }

    // per-thread gate constants: cols c = (2w+i2)*8 + (lane&3)*2 + {0,1}
    const float* __restrict__ thp = (gate == 0) ? thf : (gate == 1) ? thi
                                    : (gate == 2) ? thu : tho;
    const float* __restrict__ scp = (gate == 0) ? scf : (gate == 1) ? sci
                                    : (gate == 2) ? scu : sco;
    float thv[2][2], scv[2][2];
#pragma unroll
    for (int i2 = 0; i2 < 2; i2++) {
        int cc = (2 * w + i2) * 8 + (lane & 3) * 2;
        thv[i2][0] = thp[j0 + (cc & 31)];
        thv[i2][1] = thp[j0 + ((cc + 1) & 31)];
        scv[i2][0] = scp[j0 + (cc & 31)];
        scv[i2][1] = scp[j0 + ((cc + 1) & 31)];
    }
    const float va = (gate == 2) ? 2.0f : 1.0f;
    const float vb = (gate == 2) ? 2.0f : 1.0f;
    const float vc = (gate == 2) ? -1.0f : 0.0f;

    // c-state: 2 per thread. s = t + p*256 -> b_l = s>>5, jj = s&31
    float c_reg[2];
#pragma unroll
    for (int p = 0; p < 2; p++) {
        int s = t + p * 256;
        c_reg[p] = c0[(size_t)(bg * 16 + (s >> 5)) * 256 + j0 + (s & 31)];
    }

    __syncthreads();

    for (int ts = 0; ts < SEQ; ts++) {
        const int rp = ts & 1, wp2 = (ts + 1) & 1;

        // xw prefetch: rows (lane>>2), (lane>>2)+8 ; 2 nf each
        float2 xwv[2][2];
#pragma unroll
        for (int rr = 0; rr < 2; rr++) {
            int b = bg * 16 + (lane >> 2) + rr * 8;
#pragma unroll
            for (int i2 = 0; i2 < 2; i2++) {
                int cc = (2 * w + i2) * 8 + (lane & 3) * 2;
                int n = gate * 256 + j0 + (cc & 31);
                xwv[rr][i2] = __ldg((const float2*)&g_xw[((size_t)ts * BATCH + b) * N4 + n]);
            }
        }

        // ---- GEMM 16 x 128 x 256 via mma ----
        float acc[2][4];
#pragma unroll
        for (int i2 = 0; i2 < 2; i2++)
#pragma unroll
            for (int q = 0; q < 4; q++) acc[i2][q] = 0.0f;

        const uint32_t* __restrict__ fhi = g_hfhi[rp][bg];
        const uint32_t* __restrict__ flo = g_hflo[rp][bg];
#pragma unroll 4
        for (int ks = 0; ks < 16; ks++) {
            uint32_t ah[4], al[4];
            *(uint4*)ah = __ldcg((const uint4*)&fhi[(ks * 32 + lane) * 4]);
            *(uint4*)al = __ldcg((const uint4*)&flo[(ks * 32 + lane) * 4]);
#pragma unroll
            for (int i2 = 0; i2 < 2; i2++) {
                int nf = 2 * w + i2;
                uint32_t bh[2], bl[2];
                *(uint2*)bh = *(const uint2*)&Bf_hi[((ks * 16 + nf) * 32 + lane) * 2];
                *(uint2*)bl = *(const uint2*)&Bf_lo[((ks * 16 + nf) * 32 + lane) * 2];
                mma16816(acc[i2], ah, bh);
                mma16816(acc[i2], ah, bl);
                mma16816(acc[i2], al, bh);
            }
        }

        // ---- nonlinearities -> g_s ----
#pragma unroll
        for (int i2 = 0; i2 < 2; i2++) {
            int cc = (2 * w + i2) * 8 + (lane & 3) * 2;
#pragma unroll
            for (int rr = 0; rr < 2; rr++) {
                int row = (lane >> 2) + rr * 8;
                float z0 = acc[i2][rr * 2]     + xwv[rr][i2].x;
                float z1 = acc[i2][rr * 2 + 1] + xwv[rr][i2].y;
                float q0 = sigmoidf_(__sinf(z0 * thv[i2][0]) * scv[i2][0]);
                float q1 = sigmoidf_(__sinf(z1 * thv[i2][1]) * scv[i2][1]);
                g_s[row * 132 + cc]     = va * sigmoidf_(vb * q0) + vc;
                g_s[row * 132 + cc + 1] = va * sigmoidf_(vb * q1) + vc;
            }
        }
        __syncthreads();

        // ---- state update: 2 states per thread ----
#pragma unroll
        for (int p = 0; p < 2; p++) {
            int s = t + p * 256;
            int b_l = s >> 5, jj = s & 31;
            float fv = g_s[b_l * 132 +       jj];
            float iv = g_s[b_l * 132 +  32 + jj];
            float uv = g_s[b_l * 132 +  64 + jj];
            float ov = g_s[b_l * 132 +  96 + jj];
            float cc = fv * c_reg[p] + iv * uv;
            c_reg[p] = cc;
            float h = ov * tanhf_fast(cc);

            int b = bg * 16 + b_l;
            int j = j0 + jj;
            out[((size_t)ts * BATCH + b) * HID + j] = h;

            // h -> fragment buffer (parity wp2)
            int ks = j >> 4, kk = j & 15;
            int lp = (b_l & 7) * 4 + ((kk & 7) >> 1);
            int rg = ((b_l >> 3) & 1) | ((kk >> 3) << 1);
            int fi = (ks * 32 + lp) * 4 + rg;
            __nv_bfloat16 hh = __float2bfloat16(h);
            __nv_bfloat16 hl = __float2bfloat16(h - __bfloat162float(hh));
            ((__nv_bfloat16*)&g_hfhi[wp2][bg][fi])[kk & 1] = hh;
            ((__nv_bfloat16*)&g_hflo[wp2][bg][fi])[kk & 1] = hl;

            if (ts == SEQ - 1) {
                size_t sidx = (size_t)b * HID + j;
                out[OUT_SEQ_ELEMS + sidx] = h;
                out[OUT_SEQ_ELEMS + (size_t)BATCH * HID + sidx] = cc;
            }
        }

        if (ts < SEQ - 1) group_barrier(bg);
    }
}

// ---------------------------------------------------------------------------
extern "C" void kernel_launch(void* const* d_in, const int* in_sizes, int n_in,
                              void* d_out, int out_size)
{
    (void)in_sizes; (void)n_in; (void)out_size;
    const float* inputs = (const float*)d_in[0];
    const float* h0  = (const float*)d_in[1];
    const float* c0  = (const float*)d_in[2];
    const float* Wf  = (const float*)d_in[3];
    const float* bf  = (const float*)d_in[4];
    const float* thf = (const float*)d_in[5];
    const float* scf = (const float*)d_in[6];
    const float* Wi  = (const float*)d_in[7];
    const float* bi  = (const float*)d_in[8];
    const float* thi = (const float*)d_in[9];
    const float* sci = (const float*)d_in[10];
    const float* Wu  = (const float*)d_in[11];
    const float* bu  = (const float*)d_in[12];
    const float* thu = (const float*)d_in[13];
    const float* scu = (const float*)d_in[14];
    const float* Wo  = (const float*)d_in[15];
    const float* bo  = (const float*)d_in[16];
    const float* tho = (const float*)d_in[17];
    const float* sco = (const float*)d_in[18];
    float* out = (float*)d_out;

    conv_x<<<(GM_M * 256) / (256 * 4), 256>>>(inputs);
    conv_w<<<(1024 * 256) / (256 * 4), 256>>>(Wf, Wi, Wu, Wo);
    conv_h0<<<256, 256>>>(h0);

    dim3 g1(8, GM_M / 128);
    xw_mma<<<g1, 256>>>(bf, bi, bu, bo);

    const int smem2 = 16384 * 4 * 2 + 16 * 132 * 4;   // 131072 + 8448
    cudaFuncSetAttribute(qlstm_steps, cudaFuncAttributeMaxDynamicSharedMemorySize, smem2);
    qlstm_steps<<<128, 256, smem2>>>(c0, Wf, Wi, Wu, Wo,
                                     thf, scf, thi, sci, thu, scu, tho, sco,
                                     out);
}